// round 2
// baseline (speedup 1.0000x reference)
#include <cuda_runtime.h>
#include <cstdint>

#define THREADS 128
#define ROWS 128

typedef unsigned long long ull;

// ---- packed f32x2 helpers (Blackwell dual-fp32 pipe) ----
__device__ __forceinline__ ull f2x2_fma(ull a, ull b, ull c) {
    ull d; asm("fma.rn.f32x2 %0, %1, %2, %3;" : "=l"(d) : "l"(a), "l"(b), "l"(c)); return d;
}
__device__ __forceinline__ ull f2x2_add(ull a, ull b) {
    ull d; asm("add.rn.f32x2 %0, %1, %2;" : "=l"(d) : "l"(a), "l"(b)); return d;
}
__device__ __forceinline__ ull f2x2_pack(float lo, float hi) {
    ull d; asm("mov.b64 %0, {%1, %2};" : "=l"(d) : "f"(lo), "f"(hi)); return d;
}
__device__ __forceinline__ void f2x2_unpack(ull v, float& lo, float& hi) {
    asm("mov.b64 {%0, %1}, %2;" : "=f"(lo), "=f"(hi) : "l"(v));
}

// Shared memory layout (in floats)
#define OW1T   0        // w1 transposed [128][68]  (pad 64->68 keeps 16B row align, kills store conflicts)
#define OW2    8704     // w2 [128][32]
#define OB1    12800    // [128]
#define OB2    12928    // [32]
#define OMEAN  12960    // [64]
#define OSCL   13024    // [64]  1/(std+1e-8)
#define OENCW  13088    // [8][8][4]
#define OENCB  13344    // [8][4]
#define OSRCW  13376    // [4][16]
#define OSRCB  13440    // [16]
#define ODSTW  13456    // [4][16]
#define ODSTB  13520    // [16]
#define ODECW  13536    // [96][2]
#define ODECB  13728    // [2]
#define OXS    13732    // x transposed [64][129]
#define SMEM_FLOATS (OXS + 64*129)
#define SMEM_BYTES  (SMEM_FLOATS * 4)

__global__ void __launch_bounds__(THREADS)
ggan_kernel(const float* __restrict__ gx,
            const float* __restrict__ g_mean, const float* __restrict__ g_std,
            const float* __restrict__ g_w1,   const float* __restrict__ g_b1,
            const float* __restrict__ g_w2,   const float* __restrict__ g_b2,
            const float* __restrict__ g_encw, const float* __restrict__ g_encb,
            const float* __restrict__ g_srcw, const float* __restrict__ g_srcb,
            const float* __restrict__ g_dstw, const float* __restrict__ g_dstb,
            const float* __restrict__ g_decw, const float* __restrict__ g_decb,
            float2* __restrict__ gout)
{
    extern __shared__ float sm[];
    float* w1t  = sm + OW1T;
    float* w2s  = sm + OW2;
    float* b1s  = sm + OB1;
    float* b2s  = sm + OB2;
    float* mnv  = sm + OMEAN;
    float* sclv = sm + OSCL;
    float* encw = sm + OENCW;
    float* encb = sm + OENCB;
    float* srcw = sm + OSRCW;
    float* srcb = sm + OSRCB;
    float* dstw = sm + ODSTW;
    float* dstb = sm + ODSTB;
    float* decw = sm + ODECW;
    float* decb = sm + ODECB;
    float* xs   = sm + OXS;

    const int tid = threadIdx.x;

    // ---- stage weights to shared ----
    for (int i = tid; i < 64 * 128; i += THREADS) {
        int d = i >> 7, h = i & 127;
        w1t[h * 68 + d] = g_w1[i];
    }
    for (int i = tid; i < 128 * 32; i += THREADS) w2s[i] = g_w2[i];
    b1s[tid] = g_b1[tid];
    for (int i = tid; i < 256; i += THREADS) encw[i] = g_encw[i];
    for (int i = tid; i < 192; i += THREADS) decw[i] = g_decw[i];
    if (tid < 64) {
        mnv[tid]  = g_mean[tid];
        sclv[tid] = 1.0f / (g_std[tid] + 1e-8f);
        srcw[tid] = g_srcw[tid];
        dstw[tid] = g_dstw[tid];
    }
    if (tid < 32) { b2s[tid] = g_b2[tid]; encb[tid] = g_encb[tid]; }
    if (tid < 16) { srcb[tid] = g_srcb[tid]; dstb[tid] = g_dstb[tid]; }
    if (tid < 2)  decb[tid] = g_decb[tid];

    // ---- stage x tile transposed (coalesced GMEM, conflict-free later reads) ----
    const size_t rowBase = (size_t)blockIdx.x * ROWS;
    const float4* xg = (const float4*)(gx + rowBase * 64);
    for (int i = tid; i < ROWS * 16; i += THREADS) {
        float4 v = xg[i];
        int r = i >> 4, c = (i & 15) * 4;
        xs[(c + 0) * 129 + r] = v.x;
        xs[(c + 1) * 129 + r] = v.y;
        xs[(c + 2) * 129 + r] = v.z;
        xs[(c + 3) * 129 + r] = v.w;
    }
    __syncthreads();

    const int r = tid;

    // ---- pack x into f32x2 registers ----
    ull xp[32];
    #pragma unroll
    for (int j = 0; j < 32; j++)
        xp[j] = f2x2_pack(xs[(2 * j) * 129 + r], xs[(2 * j + 1) * 129 + r]);

    // ---- fused MLP: layer1 (64->128, relu) streamed into layer2 accumulators (->32) ----
    ull acc2[16];
    #pragma unroll
    for (int o = 0; o < 16; o++) acc2[o] = f2x2_pack(b2s[2 * o], b2s[2 * o + 1]);

    #pragma unroll 4
    for (int hid = 0; hid < 128; hid++) {
        const ull* wrow = (const ull*)(w1t + hid * 68);
        ull a0 = 0ull, a1 = 0ull, a2 = 0ull, a3 = 0ull;
        #pragma unroll
        for (int j = 0; j < 32; j += 4) {
            a0 = f2x2_fma(xp[j + 0], wrow[j + 0], a0);
            a1 = f2x2_fma(xp[j + 1], wrow[j + 1], a1);
            a2 = f2x2_fma(xp[j + 2], wrow[j + 2], a2);
            a3 = f2x2_fma(xp[j + 3], wrow[j + 3], a3);
        }
        ull s = f2x2_add(f2x2_add(a0, a1), f2x2_add(a2, a3));
        float lo, hi; f2x2_unpack(s, lo, hi);
        float act = fmaxf(lo + hi + b1s[hid], 0.0f);
        ull ap = f2x2_pack(act, act);
        const ull* w2row = (const ull*)(w2s + hid * 32);
        #pragma unroll
        for (int o = 0; o < 16; o++)
            acc2[o] = f2x2_fma(ap, w2row[o], acc2[o]);
    }

    // ---- decoder accumulators; fold x_hat contribution immediately (frees regs) ----
    float o0 = decb[0], o1 = decb[1];
    #pragma unroll
    for (int o = 0; o < 16; o++) {
        float a, b; f2x2_unpack(acc2[o], a, b);
        a = fmaxf(a, 0.0f); b = fmaxf(b, 0.0f);
        o0 += a * decw[(2 * o) * 2 + 0] + b * decw[(2 * o + 1) * 2 + 0];
        o1 += a * decw[(2 * o) * 2 + 1] + b * decw[(2 * o + 1) * 2 + 1];
    }

    // ---- per-group encoders on normalized x ----
    float hv[32];
    #pragma unroll
    for (int g = 0; g < 8; g++) {
        float xn[8];
        #pragma unroll
        for (int f = 0; f < 8; f++) {
            int d = g * 8 + f;
            xn[f] = (xs[d * 129 + r] - mnv[d]) * sclv[d];
        }
        #pragma unroll
        for (int e = 0; e < 4; e++) {
            float s = encb[g * 4 + e];
            #pragma unroll
            for (int f = 0; f < 8; f++)
                s += xn[f] * encw[g * 32 + f * 4 + e];
            hv[g * 4 + e] = fmaxf(s, 0.0f);
        }
    }

    // fold h contribution to decoder
    #pragma unroll
    for (int i = 0; i < 32; i++) {
        o0 += hv[i] * decw[(32 + i) * 2 + 0];
        o1 += hv[i] * decw[(32 + i) * 2 + 1];
    }

    // ---- GAT multi-head attention over the 8 group nodes ----
    float att[32];
    #pragma unroll
    for (int i = 0; i < 32; i++) att[i] = 0.0f;
    const float inv_sqrt8 = 0.35355339059327373f;

    #pragma unroll
    for (int hd = 0; hd < 2; hd++) {
        // dst vectors for this head: dstv[k][a]
        float dstv[64];
        #pragma unroll
        for (int k = 0; k < 8; k++) {
            #pragma unroll
            for (int a = 0; a < 8; a++) {
                float s = dstb[hd * 8 + a];
                #pragma unroll
                for (int e = 0; e < 4; e++)
                    s += hv[k * 4 + e] * dstw[e * 16 + hd * 8 + a];
                dstv[k * 8 + a] = s;
            }
        }
        #pragma unroll
        for (int g = 0; g < 8; g++) {
            float srcg[8];
            #pragma unroll
            for (int a = 0; a < 8; a++) {
                float s = srcb[hd * 8 + a];
                #pragma unroll
                for (int e = 0; e < 4; e++)
                    s += hv[g * 4 + e] * srcw[e * 16 + hd * 8 + a];
                srcg[a] = s;
            }
            float sc[8], mx = -1e30f;
            #pragma unroll
            for (int k = 0; k < 8; k++) {
                float s = 0.0f;
                #pragma unroll
                for (int a = 0; a < 8; a++) s += srcg[a] * dstv[k * 8 + a];
                sc[k] = s * inv_sqrt8;
                mx = fmaxf(mx, sc[k]);
            }
            float ssum = 0.0f;
            #pragma unroll
            for (int k = 0; k < 8; k++) { sc[k] = __expf(sc[k] - mx); ssum += sc[k]; }
            float inv = 1.0f / ssum;
            #pragma unroll
            for (int k = 0; k < 8; k++) {
                float w = sc[k] * inv;
                #pragma unroll
                for (int e = 0; e < 4; e++)
                    att[g * 4 + e] += w * hv[k * 4 + e];
            }
        }
    }

    // fold att_out contribution to decoder and store
    #pragma unroll
    for (int i = 0; i < 32; i++) {
        o0 += att[i] * decw[(64 + i) * 2 + 0];
        o1 += att[i] * decw[(64 + i) * 2 + 1];
    }

    gout[rowBase + r] = make_float2(o0, o1);
}

extern "C" void kernel_launch(void* const* d_in, const int* in_sizes, int n_in,
                              void* d_out, int out_size)
{
    const float* x      = (const float*)d_in[0];
    const float* nmean  = (const float*)d_in[1];
    const float* nstd   = (const float*)d_in[2];
    const float* w1     = (const float*)d_in[3];
    const float* b1     = (const float*)d_in[4];
    const float* w2     = (const float*)d_in[5];
    const float* b2     = (const float*)d_in[6];
    const float* encwp  = (const float*)d_in[7];
    const float* encbp  = (const float*)d_in[8];
    const float* srcwp  = (const float*)d_in[9];
    const float* srcbp  = (const float*)d_in[10];
    const float* dstwp  = (const float*)d_in[11];
    const float* dstbp  = (const float*)d_in[12];
    const float* decwp  = (const float*)d_in[13];
    const float* decbp  = (const float*)d_in[14];
    float2* out = (float2*)d_out;

    int B = in_sizes[0] / 64;
    int grid = B / ROWS;

    // host-side attribute set; not a stream op, safe under graph capture
    cudaFuncSetAttribute(ggan_kernel, cudaFuncAttributeMaxDynamicSharedMemorySize, SMEM_BYTES);

    ggan_kernel<<<grid, THREADS, SMEM_BYTES>>>(
        x, nmean, nstd, w1, b1, w2, b2,
        encwp, encbp, srcwp, srcbp, dstwp, dstbp, decwp, decbp, out);
}

// round 4
// speedup vs baseline: 1.3877x; 1.3877x over previous
#include <cuda_runtime.h>
#include <cstdint>

#define THREADS 128
#define ROWS 128

typedef unsigned long long ull;

// ---- packed f32x2 helpers (Blackwell dual-fp32 pipe) ----
__device__ __forceinline__ ull f2x2_fma(ull a, ull b, ull c) {
    ull d; asm("fma.rn.f32x2 %0, %1, %2, %3;" : "=l"(d) : "l"(a), "l"(b), "l"(c)); return d;
}
__device__ __forceinline__ ull f2x2_add(ull a, ull b) {
    ull d; asm("add.rn.f32x2 %0, %1, %2;" : "=l"(d) : "l"(a), "l"(b)); return d;
}
__device__ __forceinline__ ull f2x2_pack(float lo, float hi) {
    ull d; asm("mov.b64 %0, {%1, %2};" : "=l"(d) : "f"(lo), "f"(hi)); return d;
}
__device__ __forceinline__ void f2x2_unpack(ull v, float& lo, float& hi) {
    asm("mov.b64 {%0, %1}, %2;" : "=f"(lo), "=f"(hi) : "l"(v));
}

// ---- shared memory layout (float offsets) ----
#define OW1T   0        // w1 transposed [128][68]   (row stride 68 floats = 272B, 16B aligned)
#define OB1    8704     // [128]
#define OB2    8832     // [32]
#define OMEAN  8864     // [64]
#define OSCL   8928     // [64]
#define OENCW  8992     // [8][8][4]
#define OENCB  9248     // [8][4]
#define OSRCW  9280     // [4][16]
#define OSRCB  9344     // [16]
#define ODSTW  9360     // [4][16]
#define ODSTB  9424     // [16]
#define ODECW  9440     // [96][2]
#define ODECB  9632     // [2]
#define OATTA  9634     // A[2][4][4]  (head, e, e')   pre-scaled by 1/sqrt(8)
#define OATTV  9666     // V[2][4]                     pre-scaled by 1/sqrt(8)
#define OXS    9676     // x transposed [64][129]; RE-USED as w2 [128][32] during the MLP phase
#define SMEM_FLOATS (OXS + 64*129)     // 17932 floats
#define SMEM_BYTES  (SMEM_FLOATS * 4)  // 71728 B -> 3 CTAs/SM

__global__ void __launch_bounds__(THREADS, 3)
ggan_kernel(const float* __restrict__ gx,
            const float* __restrict__ g_mean, const float* __restrict__ g_std,
            const float* __restrict__ g_w1,   const float* __restrict__ g_b1,
            const float* __restrict__ g_w2,   const float* __restrict__ g_b2,
            const float* __restrict__ g_encw, const float* __restrict__ g_encb,
            const float* __restrict__ g_srcw, const float* __restrict__ g_srcb,
            const float* __restrict__ g_dstw, const float* __restrict__ g_dstb,
            const float* __restrict__ g_decw, const float* __restrict__ g_decb,
            float2* __restrict__ gout)
{
    extern __shared__ float sm[];
    float* w1t  = sm + OW1T;
    float* b1s  = sm + OB1;
    float* b2s  = sm + OB2;
    float* mnv  = sm + OMEAN;
    float* sclv = sm + OSCL;
    float* encw = sm + OENCW;
    float* encb = sm + OENCB;
    float* srcw = sm + OSRCW;
    float* srcb = sm + OSRCB;
    float* dstw = sm + ODSTW;
    float* dstb = sm + ODSTB;
    float* decw = sm + ODECW;
    float* decb = sm + ODECB;
    float* attA = sm + OATTA;
    float* attV = sm + OATTV;
    float* xs   = sm + OXS;   // phase 1: x transposed; phase 2: w2
    float* w2s  = sm + OXS;

    const int tid = threadIdx.x;
    const float inv_sqrt8 = 0.35355339059327373f;

    // ================= stage weights (except w2) + x tile =================
    for (int i = tid; i < 64 * 128; i += THREADS) {
        int d = i >> 7, h = i & 127;
        w1t[h * 68 + d] = g_w1[i];
    }
    b1s[tid] = g_b1[tid];
    for (int i = tid; i < 256; i += THREADS) encw[i] = g_encw[i];
    for (int i = tid; i < 192; i += THREADS) decw[i] = g_decw[i];
    if (tid < 64) {
        mnv[tid]  = g_mean[tid];
        sclv[tid] = 1.0f / (g_std[tid] + 1e-8f);
        srcw[tid] = g_srcw[tid];
        dstw[tid] = g_dstw[tid];
    }
    if (tid < 32) { b2s[tid] = g_b2[tid]; encb[tid] = g_encb[tid]; }
    if (tid < 16) { srcb[tid] = g_srcb[tid]; dstb[tid] = g_dstb[tid]; }
    if (tid < 2)  decb[tid] = g_decb[tid];

    const size_t rowBase = (size_t)blockIdx.x * ROWS;
    const float4* xg = (const float4*)(gx + rowBase * 64);
    for (int i = tid; i < ROWS * 16; i += THREADS) {
        float4 v = xg[i];
        int r0 = i >> 4, c = (i & 15) * 4;
        xs[(c + 0) * 129 + r0] = v.x;
        xs[(c + 1) * 129 + r0] = v.y;
        xs[(c + 2) * 129 + r0] = v.z;
        xs[(c + 3) * 129 + r0] = v.w;
    }
    __syncthreads();

    // ================= precompute attention tables =================
    // score'_gk(h) = h_g^T A h_k + v . h_k   (k-independent terms cancel in softmax)
    // A[h][e][e'] = (1/sqrt8) * sum_a srcw[e][h*8+a] * dstw[e'][h*8+a]
    // V[h][e']    = (1/sqrt8) * sum_a srcb[h*8+a]    * dstw[e'][h*8+a]
    if (tid < 32) {
        int h = tid >> 4, e = (tid >> 2) & 3, e2 = tid & 3;
        float s = 0.0f;
        #pragma unroll
        for (int a = 0; a < 8; a++)
            s += srcw[e * 16 + h * 8 + a] * dstw[e2 * 16 + h * 8 + a];
        attA[tid] = s * inv_sqrt8;
    } else if (tid < 40) {
        int h = (tid - 32) >> 2, e2 = (tid - 32) & 3;
        float s = 0.0f;
        #pragma unroll
        for (int a = 0; a < 8; a++)
            s += srcb[h * 8 + a] * dstw[e2 * 16 + h * 8 + a];
        attV[tid - 32] = s * inv_sqrt8;
    }

    const int r = tid;

    // ================= per-group encoders =================
    float hv[32];
    #pragma unroll
    for (int g = 0; g < 8; g++) {
        float xn[8];
        #pragma unroll
        for (int f = 0; f < 8; f++) {
            int d = g * 8 + f;
            xn[f] = (xs[d * 129 + r] - mnv[d]) * sclv[d];
        }
        #pragma unroll
        for (int e = 0; e < 4; e++) {
            float s = encb[g * 4 + e];
            #pragma unroll
            for (int f = 0; f < 8; f++)
                s += xn[f] * encw[g * 32 + f * 4 + e];
            hv[g * 4 + e] = fmaxf(s, 0.0f);
        }
    }

    // decoder accumulators; fold h contribution now
    float o0 = decb[0], o1 = decb[1];
    #pragma unroll
    for (int i = 0; i < 32; i++) {
        o0 += hv[i] * decw[(32 + i) * 2 + 0];
        o1 += hv[i] * decw[(32 + i) * 2 + 1];
    }

    __syncthreads();   // attA/attV visible

    // ================= GAT attention (factored form) =================
    ull hvp[16];
    #pragma unroll
    for (int k = 0; k < 16; k++) hvp[k] = f2x2_pack(hv[2 * k], hv[2 * k + 1]);
    ull attp[16];
    #pragma unroll
    for (int k = 0; k < 16; k++) attp[k] = 0ull;

    #pragma unroll
    for (int hd = 0; hd < 2; hd++) {
        const float* Ah = attA + hd * 16;
        const float* Vh = attV + hd * 4;
        float t[32], q[8];
        #pragma unroll
        for (int k = 0; k < 8; k++) {
            float s = 0.0f;
            #pragma unroll
            for (int e = 0; e < 4; e++) s += Vh[e] * hv[k * 4 + e];
            q[k] = s;
            #pragma unroll
            for (int e = 0; e < 4; e++) {
                float u = 0.0f;
                #pragma unroll
                for (int e2 = 0; e2 < 4; e2++)
                    u += Ah[e * 4 + e2] * hv[k * 4 + e2];
                t[k * 4 + e] = u;
            }
        }
        #pragma unroll
        for (int g = 0; g < 8; g++) {
            float sc[8], mx = -1e30f;
            #pragma unroll
            for (int k = 0; k < 8; k++) {
                float s = q[k];
                #pragma unroll
                for (int e = 0; e < 4; e++)
                    s += hv[g * 4 + e] * t[k * 4 + e];
                sc[k] = s;
                mx = fmaxf(mx, s);
            }
            float ssum = 0.0f;
            #pragma unroll
            for (int k = 0; k < 8; k++) { sc[k] = __expf(sc[k] - mx); ssum += sc[k]; }
            float inv = 1.0f / ssum;
            #pragma unroll
            for (int k = 0; k < 8; k++) {
                float w = sc[k] * inv;
                ull wp = f2x2_pack(w, w);
                attp[g * 2 + 0] = f2x2_fma(wp, hvp[k * 2 + 0], attp[g * 2 + 0]);
                attp[g * 2 + 1] = f2x2_fma(wp, hvp[k * 2 + 1], attp[g * 2 + 1]);
            }
        }
    }

    // fold att_out contribution
    #pragma unroll
    for (int i = 0; i < 16; i++) {
        float a, b; f2x2_unpack(attp[i], a, b);
        o0 += a * decw[(64 + 2 * i) * 2 + 0] + b * decw[(64 + 2 * i + 1) * 2 + 0];
        o1 += a * decw[(64 + 2 * i) * 2 + 1] + b * decw[(64 + 2 * i + 1) * 2 + 1];
    }

    // ================= pack x, then recycle xs region as w2 =================
    ull xp[32];
    #pragma unroll
    for (int j = 0; j < 32; j++)
        xp[j] = f2x2_pack(xs[(2 * j) * 129 + r], xs[(2 * j + 1) * 129 + r]);

    __syncthreads();   // everyone done reading xs
    {
        const float4* w2g = (const float4*)g_w2;
        float4* w2sh = (float4*)w2s;
        for (int i = tid; i < 1024; i += THREADS) w2sh[i] = w2g[i];
    }
    __syncthreads();   // w2 staged

    // ================= fused MLP (64->128 relu ->32) =================
    ull acc2[16];
    #pragma unroll
    for (int o = 0; o < 16; o++) acc2[o] = f2x2_pack(b2s[2 * o], b2s[2 * o + 1]);

    #pragma unroll 2
    for (int hid = 0; hid < 128; hid++) {
        const ulonglong2* wrow = (const ulonglong2*)(w1t + hid * 68);
        ull a0 = 0ull, a1 = 0ull, a2 = 0ull, a3 = 0ull;
        #pragma unroll
        for (int j = 0; j < 16; j += 2) {
            ulonglong2 wa = wrow[j];
            ulonglong2 wb = wrow[j + 1];
            a0 = f2x2_fma(xp[2 * j + 0], wa.x, a0);
            a1 = f2x2_fma(xp[2 * j + 1], wa.y, a1);
            a2 = f2x2_fma(xp[2 * j + 2], wb.x, a2);
            a3 = f2x2_fma(xp[2 * j + 3], wb.y, a3);
        }
        ull s = f2x2_add(f2x2_add(a0, a1), f2x2_add(a2, a3));
        float lo, hi; f2x2_unpack(s, lo, hi);
        float act = fmaxf(lo + hi + b1s[hid], 0.0f);
        ull ap = f2x2_pack(act, act);
        const ulonglong2* w2row = (const ulonglong2*)(w2s + hid * 32);
        #pragma unroll
        for (int j = 0; j < 8; j++) {
            ulonglong2 w = w2row[j];
            acc2[2 * j + 0] = f2x2_fma(ap, w.x, acc2[2 * j + 0]);
            acc2[2 * j + 1] = f2x2_fma(ap, w.y, acc2[2 * j + 1]);
        }
    }

    // fold x_hat contribution and store
    #pragma unroll
    for (int o = 0; o < 16; o++) {
        float a, b; f2x2_unpack(acc2[o], a, b);
        a = fmaxf(a, 0.0f); b = fmaxf(b, 0.0f);
        o0 += a * decw[(2 * o) * 2 + 0] + b * decw[(2 * o + 1) * 2 + 0];
        o1 += a * decw[(2 * o) * 2 + 1] + b * decw[(2 * o + 1) * 2 + 1];
    }

    gout[rowBase + r] = make_float2(o0, o1);
}

extern "C" void kernel_launch(void* const* d_in, const int* in_sizes, int n_in,
                              void* d_out, int out_size)
{
    const float* x      = (const float*)d_in[0];
    const float* nmean  = (const float*)d_in[1];
    const float* nstd   = (const float*)d_in[2];
    const float* w1     = (const float*)d_in[3];
    const float* b1     = (const float*)d_in[4];
    const float* w2     = (const float*)d_in[5];
    const float* b2     = (const float*)d_in[6];
    const float* encwp  = (const float*)d_in[7];
    const float* encbp  = (const float*)d_in[8];
    const float* srcwp  = (const float*)d_in[9];
    const float* srcbp  = (const float*)d_in[10];
    const float* dstwp  = (const float*)d_in[11];
    const float* dstbp  = (const float*)d_in[12];
    const float* decwp  = (const float*)d_in[13];
    const float* decbp  = (const float*)d_in[14];
    float2* out = (float2*)d_out;

    int B = in_sizes[0] / 64;
    int grid = B / ROWS;

    cudaFuncSetAttribute(ggan_kernel, cudaFuncAttributeMaxDynamicSharedMemorySize, SMEM_BYTES);

    ggan_kernel<<<grid, THREADS, SMEM_BYTES>>>(
        x, nmean, nstd, w1, b1, w2, b2,
        encwp, encbp, srcwp, srcbp, dstwp, dstbp, decwp, decbp, out);
}

// round 6
// speedup vs baseline: 1.6837x; 1.2132x over previous
#include <cuda_runtime.h>
#include <cstdint>

#define THREADS 128
#define ROWS 128

typedef unsigned long long ull;

// ---- packed f32x2 helpers (Blackwell dual-fp32 pipe) ----
__device__ __forceinline__ ull f2x2_fma(ull a, ull b, ull c) {
    ull d; asm("fma.rn.f32x2 %0, %1, %2, %3;" : "=l"(d) : "l"(a), "l"(b), "l"(c)); return d;
}
__device__ __forceinline__ ull f2x2_add(ull a, ull b) {
    ull d; asm("add.rn.f32x2 %0, %1, %2;" : "=l"(d) : "l"(a), "l"(b)); return d;
}
__device__ __forceinline__ ull f2x2_pack(float lo, float hi) {
    ull d; asm("mov.b64 %0, {%1, %2};" : "=l"(d) : "f"(lo), "f"(hi)); return d;
}
__device__ __forceinline__ void f2x2_unpack(ull v, float& lo, float& hi) {
    asm("mov.b64 {%0, %1}, %2;" : "=f"(lo), "=f"(hi) : "l"(v));
}

// ---- shared memory layout (float offsets) ----
#define OW1T   0        // w1 transposed [128][68]   (row stride 68 floats, 16B aligned)
#define OB1    8704     // [128]
#define OB2    8832     // [32]
#define OMEAN  8864     // [64]
#define OSCL   8928     // [64]
#define OENCW  8992     // [8][8][4]
#define OENCB  9248     // [8][4]
#define OSRCW  9280     // [4][16]
#define OSRCB  9344     // [16]
#define ODSTW  9360     // [4][16]
#define ODSTB  9424     // [16]
#define ODECW  9440     // [96][2]
#define ODECB  9632     // [2]
#define OATTA  9634     // A[2][4][4] pre-scaled by 1/sqrt(8)
#define OATTV  9666     // V[2][4]    pre-scaled by 1/sqrt(8)
#define OMLP2  9676     // mlp decoder partials [128][2]
#define OXS    9932     // x transposed [64][129]; RE-USED as w2 [128][32] during MLP
#define SMEM_FLOATS (OXS + 64*129)     // 18188 floats
#define SMEM_BYTES  (SMEM_FLOATS * 4)  // 72752 B -> 3 CTAs/SM

__global__ void __launch_bounds__(THREADS, 3)
ggan_kernel(const float* __restrict__ gx,
            const float* __restrict__ g_mean, const float* __restrict__ g_std,
            const float* __restrict__ g_w1,   const float* __restrict__ g_b1,
            const float* __restrict__ g_w2,   const float* __restrict__ g_b2,
            const float* __restrict__ g_encw, const float* __restrict__ g_encb,
            const float* __restrict__ g_srcw, const float* __restrict__ g_srcb,
            const float* __restrict__ g_dstw, const float* __restrict__ g_dstb,
            const float* __restrict__ g_decw, const float* __restrict__ g_decb,
            float2* __restrict__ gout)
{
    extern __shared__ float sm[];
    float* w1t  = sm + OW1T;
    float* b1s  = sm + OB1;
    float* b2s  = sm + OB2;
    float* mnv  = sm + OMEAN;
    float* sclv = sm + OSCL;
    float* encw = sm + OENCW;
    float* encb = sm + OENCB;
    float* srcw = sm + OSRCW;
    float* srcb = sm + OSRCB;
    float* dstw = sm + ODSTW;
    float* dstb = sm + ODSTB;
    float* decw = sm + ODECW;
    float* decb = sm + ODECB;
    float* attA = sm + OATTA;
    float* attV = sm + OATTV;
    float* mlp2 = sm + OMLP2;
    float* xs   = sm + OXS;   // phase 1: x transposed; phase 2: w2
    float* w2s  = sm + OXS;

    const int tid = threadIdx.x;
    const float inv_sqrt8 = 0.35355339059327373f;

    // ================= stage weights (except w2) + x tile =================
    for (int i = tid; i < 64 * 128; i += THREADS) {
        int d = i >> 7, hh = i & 127;
        w1t[hh * 68 + d] = g_w1[i];
    }
    b1s[tid] = g_b1[tid];
    for (int i = tid; i < 256; i += THREADS) encw[i] = g_encw[i];
    for (int i = tid; i < 192; i += THREADS) decw[i] = g_decw[i];
    if (tid < 64) {
        mnv[tid]  = g_mean[tid];
        sclv[tid] = 1.0f / (g_std[tid] + 1e-8f);
        srcw[tid] = g_srcw[tid];
        dstw[tid] = g_dstw[tid];
    }
    if (tid < 32) { b2s[tid] = g_b2[tid]; encb[tid] = g_encb[tid]; }
    if (tid < 16) { srcb[tid] = g_srcb[tid]; dstb[tid] = g_dstb[tid]; }
    if (tid < 2)  decb[tid] = g_decb[tid];

    const size_t rowBase = (size_t)blockIdx.x * ROWS;
    const float4* xg = (const float4*)(gx + rowBase * 64);
    for (int i = tid; i < ROWS * 16; i += THREADS) {
        float4 v = xg[i];
        int r0 = i >> 4, c = (i & 15) * 4;
        xs[(c + 0) * 129 + r0] = v.x;
        xs[(c + 1) * 129 + r0] = v.y;
        xs[(c + 2) * 129 + r0] = v.z;
        xs[(c + 3) * 129 + r0] = v.w;
    }
    __syncthreads();

    // ================= precompute attention tables =================
    // score'_gk = h_g^T A h_k + v . h_k   (k-independent terms cancel in softmax)
    if (tid < 32) {
        int h = tid >> 4, e = (tid >> 2) & 3, e2 = tid & 3;
        float s = 0.0f;
        #pragma unroll
        for (int a = 0; a < 8; a++)
            s += srcw[e * 16 + h * 8 + a] * dstw[e2 * 16 + h * 8 + a];
        attA[tid] = s * inv_sqrt8;
    } else if (tid < 40) {
        int h = (tid - 32) >> 2, e2 = (tid - 32) & 3;
        float s = 0.0f;
        #pragma unroll
        for (int a = 0; a < 8; a++)
            s += srcb[h * 8 + a] * dstw[e2 * 16 + h * 8 + a];
        attV[tid - 32] = s * inv_sqrt8;
    }

    const int r = tid;

    // ================= per-group encoders =================
    float hv[32];
    #pragma unroll
    for (int g = 0; g < 8; g++) {
        float xn[8];
        #pragma unroll
        for (int f = 0; f < 8; f++) {
            int d = g * 8 + f;
            xn[f] = (xs[d * 129 + r] - mnv[d]) * sclv[d];
        }
        #pragma unroll
        for (int e = 0; e < 4; e++) {
            float s = encb[g * 4 + e];
            #pragma unroll
            for (int f = 0; f < 8; f++)
                s += xn[f] * encw[g * 32 + f * 4 + e];
            hv[g * 4 + e] = fmaxf(s, 0.0f);
        }
    }

    // decoder accumulators; fold h contribution now
    float o0 = decb[0], o1 = decb[1];
    #pragma unroll
    for (int i = 0; i < 32; i++) {
        o0 += hv[i] * decw[(32 + i) * 2 + 0];
        o1 += hv[i] * decw[(32 + i) * 2 + 1];
    }

    __syncthreads();   // attA/attV visible

    // ================= GAT attention (factored form) =================
    ull hvp[16];
    #pragma unroll
    for (int k = 0; k < 16; k++) hvp[k] = f2x2_pack(hv[2 * k], hv[2 * k + 1]);
    ull attp[16];
    #pragma unroll
    for (int k = 0; k < 16; k++) attp[k] = 0ull;

    #pragma unroll
    for (int hd = 0; hd < 2; hd++) {
        const float* Ah = attA + hd * 16;
        const float* Vh = attV + hd * 4;
        float t[32], q[8];
        #pragma unroll
        for (int k = 0; k < 8; k++) {
            float s = 0.0f;
            #pragma unroll
            for (int e = 0; e < 4; e++) s += Vh[e] * hv[k * 4 + e];
            q[k] = s;
            #pragma unroll
            for (int e = 0; e < 4; e++) {
                float u = 0.0f;
                #pragma unroll
                for (int e2 = 0; e2 < 4; e2++)
                    u += Ah[e * 4 + e2] * hv[k * 4 + e2];
                t[k * 4 + e] = u;
            }
        }
        #pragma unroll
        for (int g = 0; g < 8; g++) {
            float sc[8], mx = -1e30f;
            #pragma unroll
            for (int k = 0; k < 8; k++) {
                float s = q[k];
                #pragma unroll
                for (int e = 0; e < 4; e++)
                    s += hv[g * 4 + e] * t[k * 4 + e];
                sc[k] = s;
                mx = fmaxf(mx, s);
            }
            float ssum = 0.0f;
            #pragma unroll
            for (int k = 0; k < 8; k++) { sc[k] = __expf(sc[k] - mx); ssum += sc[k]; }
            float inv = 1.0f / ssum;
            #pragma unroll
            for (int k = 0; k < 8; k++) {
                float w = sc[k] * inv;
                ull wp = f2x2_pack(w, w);
                attp[g * 2 + 0] = f2x2_fma(wp, hvp[k * 2 + 0], attp[g * 2 + 0]);
                attp[g * 2 + 1] = f2x2_fma(wp, hvp[k * 2 + 1], attp[g * 2 + 1]);
            }
        }
    }

    // fold att_out contribution
    #pragma unroll
    for (int i = 0; i < 16; i++) {
        float a, b; f2x2_unpack(attp[i], a, b);
        o0 += a * decw[(64 + 2 * i) * 2 + 0] + b * decw[(64 + 2 * i + 1) * 2 + 0];
        o1 += a * decw[(64 + 2 * i) * 2 + 1] + b * decw[(64 + 2 * i + 1) * 2 + 1];
    }

    // ================= cooperative-pair MLP setup =================
    // Lane pair p = lane>>1, half h = lane&1. Pair handles rows R0 = warp*32+p
    // and R1 = warp*32+16+p; each lane owns K-half h*32..h*32+31 and output
    // half h*16..h*16+15. h=1 reads weight blocks rotated by 4 (bank-conflict
    // free vs h=0); x registers are packed in the SAME rotated order so all
    // register indices stay compile-time.
    const int lane = tid & 31, warp = tid >> 5;
    const int p = lane >> 1, h = lane & 1;
    const int R0 = warp * 32 + p, R1 = warp * 32 + 16 + p;
    const int rot = h * 4;

    ull xpa[16], xpb[16];
    #pragma unroll
    for (int i = 0; i < 8; i++) {
        int d = h * 32 + (((i + rot) & 7) << 2);
        xpa[2 * i]     = f2x2_pack(xs[(d + 0) * 129 + R0], xs[(d + 1) * 129 + R0]);
        xpa[2 * i + 1] = f2x2_pack(xs[(d + 2) * 129 + R0], xs[(d + 3) * 129 + R0]);
        xpb[2 * i]     = f2x2_pack(xs[(d + 0) * 129 + R1], xs[(d + 1) * 129 + R1]);
        xpb[2 * i + 1] = f2x2_pack(xs[(d + 2) * 129 + R1], xs[(d + 3) * 129 + R1]);
    }

    __syncthreads();   // everyone done reading xs
    {
        const float4* w2g = (const float4*)g_w2;
        float4* w2sh = (float4*)w2s;
        for (int i = tid; i < 1024; i += THREADS) w2sh[i] = w2g[i];
    }
    __syncthreads();   // w2 staged

    // ================= cooperative MLP (64->128 relu ->32) =================
    ull acc0[8], acc1[8];
    {
        const ull* b2p = (const ull*)(b2s + h * 16);
        #pragma unroll
        for (int k = 0; k < 8; k++) { acc0[k] = b2p[k]; acc1[k] = b2p[k]; }
    }

    #pragma unroll 2
    for (int hid = 0; hid < 128; hid++) {
        const ulonglong2* wrow = (const ulonglong2*)(w1t + hid * 68 + h * 32);
        ull a0 = 0ull, a1 = 0ull, a2 = 0ull, a3 = 0ull;
        #pragma unroll
        for (int i = 0; i < 8; i++) {
            ulonglong2 W = wrow[(i + rot) & 7];
            a0 = f2x2_fma(xpa[2 * i],     W.x, a0);
            a1 = f2x2_fma(xpa[2 * i + 1], W.y, a1);
            a2 = f2x2_fma(xpb[2 * i],     W.x, a2);
            a3 = f2x2_fma(xpb[2 * i + 1], W.y, a3);
        }
        float l0, h0f, l1, h1f;
        f2x2_unpack(f2x2_add(a0, a1), l0, h0f);
        f2x2_unpack(f2x2_add(a2, a3), l1, h1f);
        float s0 = l0 + h0f, s1 = l1 + h1f;
        s0 += __shfl_xor_sync(0xffffffffu, s0, 1);
        s1 += __shfl_xor_sync(0xffffffffu, s1, 1);
        float bb = b1s[hid];
        float act0 = fmaxf(s0 + bb, 0.0f);
        float act1 = fmaxf(s1 + bb, 0.0f);
        ull ap0 = f2x2_pack(act0, act0);
        ull ap1 = f2x2_pack(act1, act1);
        const ulonglong2* w2row = (const ulonglong2*)(w2s + hid * 32 + h * 16);
        #pragma unroll
        for (int k = 0; k < 4; k++) {
            ulonglong2 W = w2row[k];
            acc0[2 * k]     = f2x2_fma(ap0, W.x, acc0[2 * k]);
            acc0[2 * k + 1] = f2x2_fma(ap0, W.y, acc0[2 * k + 1]);
            acc1[2 * k]     = f2x2_fma(ap1, W.x, acc1[2 * k]);
            acc1[2 * k + 1] = f2x2_fma(ap1, W.y, acc1[2 * k + 1]);
        }
    }

    // ---- fold x_hat contribution to decoder (per-lane partial, pair-reduced) ----
    float p00 = 0.0f, p10 = 0.0f, p01 = 0.0f, p11 = 0.0f;
    #pragma unroll
    for (int j = 0; j < 8; j++) {
        int o = h * 16 + 2 * j;
        float a, b;
        f2x2_unpack(acc0[j], a, b);
        a = fmaxf(a, 0.0f); b = fmaxf(b, 0.0f);
        p00 += a * decw[o * 2 + 0] + b * decw[(o + 1) * 2 + 0];
        p10 += a * decw[o * 2 + 1] + b * decw[(o + 1) * 2 + 1];
        f2x2_unpack(acc1[j], a, b);
        a = fmaxf(a, 0.0f); b = fmaxf(b, 0.0f);
        p01 += a * decw[o * 2 + 0] + b * decw[(o + 1) * 2 + 0];
        p11 += a * decw[o * 2 + 1] + b * decw[(o + 1) * 2 + 1];
    }
    p00 += __shfl_xor_sync(0xffffffffu, p00, 1);
    p10 += __shfl_xor_sync(0xffffffffu, p10, 1);
    p01 += __shfl_xor_sync(0xffffffffu, p01, 1);
    p11 += __shfl_xor_sync(0xffffffffu, p11, 1);
    if (h == 0) {
        mlp2[R0 * 2 + 0] = p00;
        mlp2[R0 * 2 + 1] = p10;
    } else {
        mlp2[R1 * 2 + 0] = p01;
        mlp2[R1 * 2 + 1] = p11;
    }
    __syncthreads();

    o0 += mlp2[tid * 2 + 0];
    o1 += mlp2[tid * 2 + 1];
    gout[rowBase + tid] = make_float2(o0, o1);
}

extern "C" void kernel_launch(void* const* d_in, const int* in_sizes, int n_in,
                              void* d_out, int out_size)
{
    const float* x      = (const float*)d_in[0];
    const float* nmean  = (const float*)d_in[1];
    const float* nstd   = (const float*)d_in[2];
    const float* w1     = (const float*)d_in[3];
    const float* b1     = (const float*)d_in[4];
    const float* w2     = (const float*)d_in[5];
    const float* b2     = (const float*)d_in[6];
    const float* encwp  = (const float*)d_in[7];
    const float* encbp  = (const float*)d_in[8];
    const float* srcwp  = (const float*)d_in[9];
    const float* srcbp  = (const float*)d_in[10];
    const float* dstwp  = (const float*)d_in[11];
    const float* dstbp  = (const float*)d_in[12];
    const float* decwp  = (const float*)d_in[13];
    const float* decbp  = (const float*)d_in[14];
    float2* out = (float2*)d_out;

    int B = in_sizes[0] / 64;
    int grid = B / ROWS;

    cudaFuncSetAttribute(ggan_kernel, cudaFuncAttributeMaxDynamicSharedMemorySize, SMEM_BYTES);

    ggan_kernel<<<grid, THREADS, SMEM_BYTES>>>(
        x, nmean, nstd, w1, b1, w2, b2,
        encwp, encbp, srcwp, srcbp, dstwp, dstbp, decwp, decbp, out);
}

// round 7
// speedup vs baseline: 1.6841x; 1.0002x over previous
#include <cuda_runtime.h>
#include <cstdint>

#define THREADS 128
#define ROWS 128

typedef unsigned long long ull;

// ---- packed f32x2 helpers (Blackwell dual-fp32 pipe) ----
__device__ __forceinline__ ull f2x2_fma(ull a, ull b, ull c) {
    ull d; asm("fma.rn.f32x2 %0, %1, %2, %3;" : "=l"(d) : "l"(a), "l"(b), "l"(c)); return d;
}
__device__ __forceinline__ ull f2x2_add(ull a, ull b) {
    ull d; asm("add.rn.f32x2 %0, %1, %2;" : "=l"(d) : "l"(a), "l"(b)); return d;
}
__device__ __forceinline__ ull f2x2_pack(float lo, float hi) {
    ull d; asm("mov.b64 %0, {%1, %2};" : "=l"(d) : "f"(lo), "f"(hi)); return d;
}
__device__ __forceinline__ void f2x2_unpack(ull v, float& lo, float& hi) {
    asm("mov.b64 {%0, %1}, %2;" : "=f"(lo), "=f"(hi) : "l"(v));
}

// ---- shared memory layout (float offsets) ----
#define OW1T   0        // w1 transposed [128][68]   (row stride 68 floats, 16B aligned)
#define OB1    8704     // [128]
#define OB2    8832     // [32]
#define OMEAN  8864     // [64]
#define OSCL   8928     // [64]
#define OENCW  8992     // [8][8][4]
#define OENCB  9248     // [8][4]
#define OSRCW  9280     // [4][16]
#define OSRCB  9344     // [16]
#define ODSTW  9360     // [4][16]
#define ODSTB  9424     // [16]
#define ODECW  9440     // [96][2]
#define ODECB  9632     // [2]
#define OATTA  9634     // A[2][4][4] pre-scaled by 1/sqrt(8)
#define OATTV  9666     // V[2][4]    pre-scaled by 1/sqrt(8)
#define OMLP2  9676     // mlp decoder partials [128][2]
#define OXS    9932     // x transposed [64][129]; RE-USED as w2 [128][32] during MLP
#define SMEM_FLOATS (OXS + 64*129)     // 18188 floats
#define SMEM_BYTES  (SMEM_FLOATS * 4)  // 72752 B -> 3 CTAs/SM

__global__ void __launch_bounds__(THREADS, 3)
ggan_kernel(const float* __restrict__ gx,
            const float* __restrict__ g_mean, const float* __restrict__ g_std,
            const float* __restrict__ g_w1,   const float* __restrict__ g_b1,
            const float* __restrict__ g_w2,   const float* __restrict__ g_b2,
            const float* __restrict__ g_encw, const float* __restrict__ g_encb,
            const float* __restrict__ g_srcw, const float* __restrict__ g_srcb,
            const float* __restrict__ g_dstw, const float* __restrict__ g_dstb,
            const float* __restrict__ g_decw, const float* __restrict__ g_decb,
            float2* __restrict__ gout)
{
    extern __shared__ float sm[];
    float* w1t  = sm + OW1T;
    float* b1s  = sm + OB1;
    float* b2s  = sm + OB2;
    float* mnv  = sm + OMEAN;
    float* sclv = sm + OSCL;
    float* encw = sm + OENCW;
    float* encb = sm + OENCB;
    float* srcw = sm + OSRCW;
    float* srcb = sm + OSRCB;
    float* dstw = sm + ODSTW;
    float* dstb = sm + ODSTB;
    float* decw = sm + ODECW;
    float* decb = sm + ODECB;
    float* attA = sm + OATTA;
    float* attV = sm + OATTV;
    float* mlp2 = sm + OMLP2;
    float* xs   = sm + OXS;   // phase 1: x transposed; phase 2: w2
    float* w2s  = sm + OXS;

    const int tid = threadIdx.x;
    const float inv_sqrt8 = 0.35355339059327373f;

    // ================= stage weights (except w2) + x tile =================
    for (int i = tid; i < 64 * 128; i += THREADS) {
        int d = i >> 7, hh = i & 127;
        w1t[hh * 68 + d] = g_w1[i];
    }
    b1s[tid] = g_b1[tid];
    for (int i = tid; i < 256; i += THREADS) encw[i] = g_encw[i];
    for (int i = tid; i < 192; i += THREADS) decw[i] = g_decw[i];
    if (tid < 64) {
        mnv[tid]  = g_mean[tid];
        sclv[tid] = 1.0f / (g_std[tid] + 1e-8f);
        srcw[tid] = g_srcw[tid];
        dstw[tid] = g_dstw[tid];
    }
    if (tid < 32) { b2s[tid] = g_b2[tid]; encb[tid] = g_encb[tid]; }
    if (tid < 16) { srcb[tid] = g_srcb[tid]; dstb[tid] = g_dstb[tid]; }
    if (tid < 2)  decb[tid] = g_decb[tid];

    const size_t rowBase = (size_t)blockIdx.x * ROWS;
    const float4* xg = (const float4*)(gx + rowBase * 64);
    for (int i = tid; i < ROWS * 16; i += THREADS) {
        float4 v = xg[i];
        int r0 = i >> 4, c = (i & 15) * 4;
        xs[(c + 0) * 129 + r0] = v.x;
        xs[(c + 1) * 129 + r0] = v.y;
        xs[(c + 2) * 129 + r0] = v.z;
        xs[(c + 3) * 129 + r0] = v.w;
    }
    __syncthreads();

    // ================= precompute attention tables =================
    // score'_gk = h_g^T A h_k + v . h_k   (k-independent terms cancel in softmax)
    if (tid < 32) {
        int h = tid >> 4, e = (tid >> 2) & 3, e2 = tid & 3;
        float s = 0.0f;
        #pragma unroll
        for (int a = 0; a < 8; a++)
            s += srcw[e * 16 + h * 8 + a] * dstw[e2 * 16 + h * 8 + a];
        attA[tid] = s * inv_sqrt8;
    } else if (tid < 40) {
        int h = (tid - 32) >> 2, e2 = (tid - 32) & 3;
        float s = 0.0f;
        #pragma unroll
        for (int a = 0; a < 8; a++)
            s += srcb[h * 8 + a] * dstw[e2 * 16 + h * 8 + a];
        attV[tid - 32] = s * inv_sqrt8;
    }

    const int r = tid;

    // ================= per-group encoders =================
    float hv[32];
    #pragma unroll
    for (int g = 0; g < 8; g++) {
        float xn[8];
        #pragma unroll
        for (int f = 0; f < 8; f++) {
            int d = g * 8 + f;
            xn[f] = (xs[d * 129 + r] - mnv[d]) * sclv[d];
        }
        #pragma unroll
        for (int e = 0; e < 4; e++) {
            float s = encb[g * 4 + e];
            #pragma unroll
            for (int f = 0; f < 8; f++)
                s += xn[f] * encw[g * 32 + f * 4 + e];
            hv[g * 4 + e] = fmaxf(s, 0.0f);
        }
    }

    // decoder accumulators; fold h contribution now
    float o0 = decb[0], o1 = decb[1];
    #pragma unroll
    for (int i = 0; i < 32; i++) {
        o0 += hv[i] * decw[(32 + i) * 2 + 0];
        o1 += hv[i] * decw[(32 + i) * 2 + 1];
    }

    __syncthreads();   // attA/attV visible

    // ================= GAT attention (factored form) =================
    ull hvp[16];
    #pragma unroll
    for (int k = 0; k < 16; k++) hvp[k] = f2x2_pack(hv[2 * k], hv[2 * k + 1]);
    ull attp[16];
    #pragma unroll
    for (int k = 0; k < 16; k++) attp[k] = 0ull;

    #pragma unroll
    for (int hd = 0; hd < 2; hd++) {
        const float* Ah = attA + hd * 16;
        const float* Vh = attV + hd * 4;
        float t[32], q[8];
        #pragma unroll
        for (int k = 0; k < 8; k++) {
            float s = 0.0f;
            #pragma unroll
            for (int e = 0; e < 4; e++) s += Vh[e] * hv[k * 4 + e];
            q[k] = s;
            #pragma unroll
            for (int e = 0; e < 4; e++) {
                float u = 0.0f;
                #pragma unroll
                for (int e2 = 0; e2 < 4; e2++)
                    u += Ah[e * 4 + e2] * hv[k * 4 + e2];
                t[k * 4 + e] = u;
            }
        }
        #pragma unroll
        for (int g = 0; g < 8; g++) {
            float sc[8], mx = -1e30f;
            #pragma unroll
            for (int k = 0; k < 8; k++) {
                float s = q[k];
                #pragma unroll
                for (int e = 0; e < 4; e++)
                    s += hv[g * 4 + e] * t[k * 4 + e];
                sc[k] = s;
                mx = fmaxf(mx, s);
            }
            float ssum = 0.0f;
            #pragma unroll
            for (int k = 0; k < 8; k++) { sc[k] = __expf(sc[k] - mx); ssum += sc[k]; }
            float inv = 1.0f / ssum;
            #pragma unroll
            for (int k = 0; k < 8; k++) {
                float w = sc[k] * inv;
                ull wp = f2x2_pack(w, w);
                attp[g * 2 + 0] = f2x2_fma(wp, hvp[k * 2 + 0], attp[g * 2 + 0]);
                attp[g * 2 + 1] = f2x2_fma(wp, hvp[k * 2 + 1], attp[g * 2 + 1]);
            }
        }
    }

    // fold att_out contribution
    #pragma unroll
    for (int i = 0; i < 16; i++) {
        float a, b; f2x2_unpack(attp[i], a, b);
        o0 += a * decw[(64 + 2 * i) * 2 + 0] + b * decw[(64 + 2 * i + 1) * 2 + 0];
        o1 += a * decw[(64 + 2 * i) * 2 + 1] + b * decw[(64 + 2 * i + 1) * 2 + 1];
    }

    // ================= cooperative-pair MLP setup =================
    // Lane pair p = lane>>1, half h = lane&1. Pair handles rows R0 = warp*32+p
    // and R1 = warp*32+16+p; each lane owns K-half h*32..h*32+31 and output
    // half h*16..h*16+15. h=1 reads weight blocks rotated by 4 (bank-conflict
    // free vs h=0); x registers are packed in the SAME rotated order so all
    // register indices stay compile-time.
    const int lane = tid & 31, warp = tid >> 5;
    const int p = lane >> 1, h = lane & 1;
    const int R0 = warp * 32 + p, R1 = warp * 32 + 16 + p;
    const int rot = h * 4;

    ull xpa[16], xpb[16];
    #pragma unroll
    for (int i = 0; i < 8; i++) {
        int d = h * 32 + (((i + rot) & 7) << 2);
        xpa[2 * i]     = f2x2_pack(xs[(d + 0) * 129 + R0], xs[(d + 1) * 129 + R0]);
        xpa[2 * i + 1] = f2x2_pack(xs[(d + 2) * 129 + R0], xs[(d + 3) * 129 + R0]);
        xpb[2 * i]     = f2x2_pack(xs[(d + 0) * 129 + R1], xs[(d + 1) * 129 + R1]);
        xpb[2 * i + 1] = f2x2_pack(xs[(d + 2) * 129 + R1], xs[(d + 3) * 129 + R1]);
    }

    __syncthreads();   // everyone done reading xs
    {
        const float4* w2g = (const float4*)g_w2;
        float4* w2sh = (float4*)w2s;
        for (int i = tid; i < 1024; i += THREADS) w2sh[i] = w2g[i];
    }
    __syncthreads();   // w2 staged

    // ================= cooperative MLP (64->128 relu ->32) =================
    ull acc0[8], acc1[8];
    {
        const ull* b2p = (const ull*)(b2s + h * 16);
        #pragma unroll
        for (int k = 0; k < 8; k++) { acc0[k] = b2p[k]; acc1[k] = b2p[k]; }
    }

    #pragma unroll 2
    for (int hid = 0; hid < 128; hid++) {
        const ulonglong2* wrow = (const ulonglong2*)(w1t + hid * 68 + h * 32);
        ull a0 = 0ull, a1 = 0ull, a2 = 0ull, a3 = 0ull;
        #pragma unroll
        for (int i = 0; i < 8; i++) {
            ulonglong2 W = wrow[(i + rot) & 7];
            a0 = f2x2_fma(xpa[2 * i],     W.x, a0);
            a1 = f2x2_fma(xpa[2 * i + 1], W.y, a1);
            a2 = f2x2_fma(xpb[2 * i],     W.x, a2);
            a3 = f2x2_fma(xpb[2 * i + 1], W.y, a3);
        }
        float l0, h0f, l1, h1f;
        f2x2_unpack(f2x2_add(a0, a1), l0, h0f);
        f2x2_unpack(f2x2_add(a2, a3), l1, h1f);
        float s0 = l0 + h0f, s1 = l1 + h1f;
        s0 += __shfl_xor_sync(0xffffffffu, s0, 1);
        s1 += __shfl_xor_sync(0xffffffffu, s1, 1);
        float bb = b1s[hid];
        float act0 = fmaxf(s0 + bb, 0.0f);
        float act1 = fmaxf(s1 + bb, 0.0f);
        ull ap0 = f2x2_pack(act0, act0);
        ull ap1 = f2x2_pack(act1, act1);
        const ulonglong2* w2row = (const ulonglong2*)(w2s + hid * 32 + h * 16);
        #pragma unroll
        for (int k = 0; k < 4; k++) {
            ulonglong2 W = w2row[k];
            acc0[2 * k]     = f2x2_fma(ap0, W.x, acc0[2 * k]);
            acc0[2 * k + 1] = f2x2_fma(ap0, W.y, acc0[2 * k + 1]);
            acc1[2 * k]     = f2x2_fma(ap1, W.x, acc1[2 * k]);
            acc1[2 * k + 1] = f2x2_fma(ap1, W.y, acc1[2 * k + 1]);
        }
    }

    // ---- fold x_hat contribution to decoder (per-lane partial, pair-reduced) ----
    float p00 = 0.0f, p10 = 0.0f, p01 = 0.0f, p11 = 0.0f;
    #pragma unroll
    for (int j = 0; j < 8; j++) {
        int o = h * 16 + 2 * j;
        float a, b;
        f2x2_unpack(acc0[j], a, b);
        a = fmaxf(a, 0.0f); b = fmaxf(b, 0.0f);
        p00 += a * decw[o * 2 + 0] + b * decw[(o + 1) * 2 + 0];
        p10 += a * decw[o * 2 + 1] + b * decw[(o + 1) * 2 + 1];
        f2x2_unpack(acc1[j], a, b);
        a = fmaxf(a, 0.0f); b = fmaxf(b, 0.0f);
        p01 += a * decw[o * 2 + 0] + b * decw[(o + 1) * 2 + 0];
        p11 += a * decw[o * 2 + 1] + b * decw[(o + 1) * 2 + 1];
    }
    p00 += __shfl_xor_sync(0xffffffffu, p00, 1);
    p10 += __shfl_xor_sync(0xffffffffu, p10, 1);
    p01 += __shfl_xor_sync(0xffffffffu, p01, 1);
    p11 += __shfl_xor_sync(0xffffffffu, p11, 1);
    if (h == 0) {
        mlp2[R0 * 2 + 0] = p00;
        mlp2[R0 * 2 + 1] = p10;
    } else {
        mlp2[R1 * 2 + 0] = p01;
        mlp2[R1 * 2 + 1] = p11;
    }
    __syncthreads();

    o0 += mlp2[tid * 2 + 0];
    o1 += mlp2[tid * 2 + 1];
    gout[rowBase + tid] = make_float2(o0, o1);
}

extern "C" void kernel_launch(void* const* d_in, const int* in_sizes, int n_in,
                              void* d_out, int out_size)
{
    const float* x      = (const float*)d_in[0];
    const float* nmean  = (const float*)d_in[1];
    const float* nstd   = (const float*)d_in[2];
    const float* w1     = (const float*)d_in[3];
    const float* b1     = (const float*)d_in[4];
    const float* w2     = (const float*)d_in[5];
    const float* b2     = (const float*)d_in[6];
    const float* encwp  = (const float*)d_in[7];
    const float* encbp  = (const float*)d_in[8];
    const float* srcwp  = (const float*)d_in[9];
    const float* srcbp  = (const float*)d_in[10];
    const float* dstwp  = (const float*)d_in[11];
    const float* dstbp  = (const float*)d_in[12];
    const float* decwp  = (const float*)d_in[13];
    const float* decbp  = (const float*)d_in[14];
    float2* out = (float2*)d_out;

    int B = in_sizes[0] / 64;
    int grid = B / ROWS;

    cudaFuncSetAttribute(ggan_kernel, cudaFuncAttributeMaxDynamicSharedMemorySize, SMEM_BYTES);

    ggan_kernel<<<grid, THREADS, SMEM_BYTES>>>(
        x, nmean, nstd, w1, b1, w2, b2,
        encwp, encbp, srcwp, srcbp, dstwp, dstbp, decwp, decbp, out);
}